// round 9
// baseline (speedup 1.0000x reference)
#include <cuda_runtime.h>

// HiPPO-LegS scan:  x_t = A_t x_{t-1} + inputs[t,b] * B_t,  x_{-1} = 0
//   inputs    : (L, 32)      float32
//   A_stacked : (L, 128,128) float32
//   B_stacked : (L, 128)     float32
//   out       : (L, 32, 128) float32
//
// Chunked parallel scan, C = 16, K = L/C:
//   Pass 1: per chunk, augmented chain [P | y] <- A_t [P | y] (+u_t), storing
//           P_t (transposed) to g_P and y_t to out each step.
//           Inner product uses packed fma.rn.f32x2 (2 fp32 FMA lanes/issue).
//   Pass 2: sequential scan over K chunk transitions with register-prefetched
//           M_k / v_k, writes chunk-start states g_S.
//   Pass 3: out[t] += P_t * S_k   (fully parallel over t).

#define NDIM 128
#define BDIM 32
#define CSZ  16
#define KMAX 64
#define LMAX 1024
#define APAD 132    // padded A-tile row stride (floats)
#define WCOLS 80    // augmented columns per block (160 split across 2 blocks)

typedef unsigned long long ull;

// scratch (__device__ globals only — no allocations allowed)
__device__ float g_P[(size_t)LMAX * NDIM * NDIM];   // [t][j][i] = P_t[i][j]  (64 MB)
__device__ float g_S[KMAX * BDIM * NDIM];           // [k][b][i] state BEFORE chunk k

// ---- packed fp32x2 helpers (Blackwell FFMA2 path) -------------------------
__device__ __forceinline__ ull fma2(ull a, ull b, ull c) {
    ull d;
    asm("fma.rn.f32x2 %0, %1, %2, %3;" : "=l"(d) : "l"(a), "l"(b), "l"(c));
    return d;
}
__device__ __forceinline__ ull pack2(float x, float y) {
    ull d;
    asm("mov.b64 %0, {%1, %2};" : "=l"(d) : "f"(x), "f"(y));
    return d;
}
__device__ __forceinline__ float2 unpack2(ull v) {
    float2 r;
    asm("mov.b64 {%0, %1}, %2;" : "=f"(r.x), "=f"(r.y) : "l"(v));
    return r;
}

// ---------------------------------------------------------------------------
// Pass 1: chunk reduction. Augmented state W = [P (128 cols) | Y (32 cols)],
// split across 2 blocks of 80 columns. grid = (2, K), block = 512.
// Thread tile: 2 rows x 10 cols (5 column-PAIRS via f32x2).
// A double-buffered in smem (prefetch next step's A during compute).
// ---------------------------------------------------------------------------
__global__ __launch_bounds__(512, 1)
void pass1_chunk(const float* __restrict__ A, const float* __restrict__ inp,
                 const float* __restrict__ Bst, float* __restrict__ outp)
{
    extern __shared__ float sm[];
    float* As = sm;                          // 2 * NDIM * APAD (double buffer)
    float* W  = sm + 2 * NDIM * APAD;        // 2 * NDIM * WCOLS (ping-pong)

    const int k   = blockIdx.y;
    const int c0  = blockIdx.x * WCOLS;      // first global augmented column
    const int tid = threadIdx.x;
    const int tx  = tid & 7;                 // 8 col-groups of 10
    const int ty  = tid >> 3;                // 64 row-groups of 2
    const int row0 = ty << 1;
    const int q0   = tx * 10;

    // init: P columns = identity columns, Y columns = 0
    for (int idx = tid; idx < NDIM * WCOLS; idx += 512) {
        int i = idx / WCOLS;
        int c = idx - i * WCOLS;
        W[idx] = (c0 + c == i) ? 1.0f : 0.0f;
    }

    // stage A_{t0} into buffer 0
    {
        const float4* Ag = reinterpret_cast<const float4*>(A + (size_t)(k * CSZ) * (NDIM * NDIM));
#pragma unroll
        for (int v = 0; v < 8; ++v) {
            int e = tid + v * 512;
            float4 val = Ag[e];
            int r  = e >> 5;
            int c4 = (e & 31) << 2;
            *reinterpret_cast<float4*>(As + r * APAD + c4) = val;
        }
    }
    __syncthreads();

    int cur = 0, ab = 0;
    for (int lt = 0; lt < CSZ; ++lt) {
        const int t = k * CSZ + lt;

        // prefetch next A into alternate buffer (overlaps with compute; the
        // end-of-step barrier drains these STS before next step reads them)
        if (lt + 1 < CSZ) {
            const float4* Ag = reinterpret_cast<const float4*>(A + (size_t)(t + 1) * (NDIM * NDIM));
            float* Ad = As + (1 - ab) * (NDIM * APAD);
#pragma unroll
            for (int v = 0; v < 8; ++v) {
                int e = tid + v * 512;
                float4 val = Ag[e];
                int r  = e >> 5;
                int c4 = (e & 31) << 2;
                *reinterpret_cast<float4*>(Ad + r * APAD + c4) = val;
            }
        }

        const float* Ac = As + ab * (NDIM * APAD);
        const float* Wo = W + cur * (NDIM * WCOLS);

        ull acc0[5], acc1[5];
#pragma unroll
        for (int p = 0; p < 5; ++p) { acc0[p] = 0ull; acc1[p] = 0ull; }

#pragma unroll 2
        for (int j = 0; j < NDIM; ++j) {
            float a0 = Ac[(row0 + 0) * APAD + j];
            float a1 = Ac[(row0 + 1) * APAD + j];
            ull a0p = pack2(a0, a0);
            ull a1p = pack2(a1, a1);
            const ull* wr = reinterpret_cast<const ull*>(Wo + j * WCOLS + q0);
#pragma unroll
            for (int p = 0; p < 5; ++p) {
                ull w = wr[p];
                acc0[p] = fma2(a0p, w, acc0[p]);
                acc1[p] = fma2(a1p, w, acc1[p]);
            }
        }

        // u-injection on batch columns + per-step global stores + Wn write
        float bv0 = Bst[t * NDIM + row0 + 0];
        float bv1 = Bst[t * NDIM + row0 + 1];
        ull bv0p = pack2(bv0, bv0);
        ull bv1p = pack2(bv1, bv1);

        float* Wn = W + (1 - cur) * (NDIM * WCOLS);
#pragma unroll
        for (int p = 0; p < 5; ++p) {
            const int cgp = c0 + q0 + 2 * p;        // even; pair (cgp, cgp+1)
            if (cgp >= NDIM) {
                ull fp = pack2(inp[t * BDIM + (cgp - NDIM)],
                               inp[t * BDIM + (cgp - NDIM) + 1]);
                acc0[p] = fma2(fp, bv0p, acc0[p]);
                acc1[p] = fma2(fp, bv1p, acc1[p]);
            }
            // transposed stores: col cgp -> (r0.x, r1.x), col cgp+1 -> (r0.y, r1.y)
            float2 r0 = unpack2(acc0[p]);
            float2 r1 = unpack2(acc1[p]);
            float2 cA = make_float2(r0.x, r1.x);
            float2 cB = make_float2(r0.y, r1.y);
            if (cgp < NDIM) {
                *reinterpret_cast<float2*>(g_P + ((size_t)t * NDIM + cgp    ) * NDIM + row0) = cA;
                *reinterpret_cast<float2*>(g_P + ((size_t)t * NDIM + cgp + 1) * NDIM + row0) = cB;
            } else {
                *reinterpret_cast<float2*>(outp + (size_t)t * (BDIM * NDIM)
                                                + (size_t)(cgp - NDIM    ) * NDIM + row0) = cA;
                *reinterpret_cast<float2*>(outp + (size_t)t * (BDIM * NDIM)
                                                + (size_t)(cgp - NDIM + 1) * NDIM + row0) = cB;
            }
            *reinterpret_cast<ull*>(Wn + (row0 + 0) * WCOLS + q0 + 2 * p) = acc0[p];
            *reinterpret_cast<ull*>(Wn + (row0 + 1) * WCOLS + q0 + 2 * p) = acc1[p];
        }

        __syncthreads();      // Wn visible; A prefetch STS drained
        cur ^= 1;
        ab  ^= 1;
    }
}

// ---------------------------------------------------------------------------
// Pass 2: sequential scan over chunk transitions; one block per batch column.
// grid = 32, block = 512. M_k / v_k register-prefetched one iteration ahead
// (loads are independent of the carried state s, so latency hides under the
// matvec + reduce + barriers of the current iteration).
// ---------------------------------------------------------------------------
__global__ __launch_bounds__(512, 1)
void pass2_scan(const float* __restrict__ outy, int K)
{
    __shared__ float s[NDIM];
    __shared__ float part[16 * NDIM];
    const int b   = blockIdx.x;
    const int tid = threadIdx.x;
    const int i0  = (tid & 31) << 2;
    const int q   = tid >> 5;            // 0..15
    const int j0  = q << 3;

    if (tid < NDIM) s[tid] = 0.0f;

    float4 mbuf[8];
    {
        const float* M0 = g_P + ((size_t)(CSZ - 1)) * (NDIM * NDIM);
#pragma unroll
        for (int jj = 0; jj < 8; ++jj)
            mbuf[jj] = *reinterpret_cast<const float4*>(M0 + (j0 + jj) * NDIM + i0);
    }
    float vreg = (tid < NDIM)
        ? outy[((size_t)(CSZ - 1)) * (BDIM * NDIM) + b * NDIM + tid] : 0.0f;
    __syncthreads();

    for (int k = 0; k < K; ++k) {
        if (tid < NDIM)
            g_S[k * (BDIM * NDIM) + b * NDIM + tid] = s[tid];  // state BEFORE chunk k

        // prefetch k+1 (independent of s) — issue before the dependent matvec
        const int kn = (k + 1 < K) ? (k + 1) : k;
        const float* Mn = g_P + ((size_t)(kn * CSZ + CSZ - 1)) * (NDIM * NDIM);
        float4 nbuf[8];
#pragma unroll
        for (int jj = 0; jj < 8; ++jj)
            nbuf[jj] = *reinterpret_cast<const float4*>(Mn + (j0 + jj) * NDIM + i0);
        float vn = (tid < NDIM)
            ? outy[((size_t)(kn * CSZ + CSZ - 1)) * (BDIM * NDIM) + b * NDIM + tid] : 0.0f;

        float4 acc = make_float4(0.f, 0.f, 0.f, 0.f);
#pragma unroll
        for (int jj = 0; jj < 8; ++jj) {
            float sj = s[j0 + jj];
            acc.x += mbuf[jj].x * sj; acc.y += mbuf[jj].y * sj;
            acc.z += mbuf[jj].z * sj; acc.w += mbuf[jj].w * sj;
        }
        *reinterpret_cast<float4*>(&part[q * NDIM + i0]) = acc;
        __syncthreads();

        if (tid < NDIM) {
            float r = vreg;
#pragma unroll
            for (int qq = 0; qq < 16; ++qq) r += part[qq * NDIM + tid];
            s[tid] = r;
        }
#pragma unroll
        for (int jj = 0; jj < 8; ++jj) mbuf[jj] = nbuf[jj];
        vreg = vn;
        __syncthreads();
    }
}

// ---------------------------------------------------------------------------
// Pass 3: out[t][b][i] += sum_j P_t[i][j] * S_k[b][j].  grid = L, block = 256.
// ---------------------------------------------------------------------------
__global__ __launch_bounds__(256, 1)
void pass3_apply(float* __restrict__ outp)
{
    __shared__ float sS[NDIM * 36];      // [j*36 + b], 16B-aligned float4 rows
    const int t   = blockIdx.x;
    const int k   = t >> 4;              // CSZ = 16
    const int tid = threadIdx.x;

    for (int idx = tid; idx < NDIM * BDIM; idx += 256) {
        int b = idx >> 7, j = idx & 127;
        sS[j * 36 + b] = g_S[k * (BDIM * NDIM) + idx];
    }
    __syncthreads();

    const int i  = tid & 127;
    const int b0 = (tid >> 7) << 4;      // 0 or 16
    const size_t obase = (size_t)t * (BDIM * NDIM);

    float acc[16];
#pragma unroll
    for (int bb = 0; bb < 16; ++bb)
        acc[bb] = outp[obase + (b0 + bb) * NDIM + i];   // y_t (written by pass1)

    const float* P = g_P + (size_t)t * (NDIM * NDIM);
#pragma unroll 4
    for (int j = 0; j < NDIM; ++j) {
        float p = P[j * NDIM + i];                       // coalesced over i
        float4 s0 = *reinterpret_cast<const float4*>(&sS[j * 36 + b0 + 0]);
        float4 s1 = *reinterpret_cast<const float4*>(&sS[j * 36 + b0 + 4]);
        float4 s2 = *reinterpret_cast<const float4*>(&sS[j * 36 + b0 + 8]);
        float4 s3 = *reinterpret_cast<const float4*>(&sS[j * 36 + b0 + 12]);
        acc[0]  += p * s0.x; acc[1]  += p * s0.y; acc[2]  += p * s0.z; acc[3]  += p * s0.w;
        acc[4]  += p * s1.x; acc[5]  += p * s1.y; acc[6]  += p * s1.z; acc[7]  += p * s1.w;
        acc[8]  += p * s2.x; acc[9]  += p * s2.y; acc[10] += p * s2.z; acc[11] += p * s2.w;
        acc[12] += p * s3.x; acc[13] += p * s3.y; acc[14] += p * s3.z; acc[15] += p * s3.w;
    }

#pragma unroll
    for (int bb = 0; bb < 16; ++bb)
        outp[obase + (b0 + bb) * NDIM + i] = acc[bb];
}

// ---------------------------------------------------------------------------
extern "C" void kernel_launch(void* const* d_in, const int* in_sizes, int n_in,
                              void* d_out, int out_size)
{
    // identify inputs by element count (A is the largest; inputs = L*32; B = L*128)
    int ia = 0;
    for (int i = 1; i < n_in; ++i)
        if (in_sizes[i] > in_sizes[ia]) ia = i;
    const float* A = (const float*)d_in[ia];
    const int L = in_sizes[ia] / (NDIM * NDIM);
    const float* inp = nullptr;
    const float* Bst = nullptr;
    for (int i = 0; i < n_in; ++i) {
        if (i == ia) continue;
        if (in_sizes[i] == L * BDIM) inp = (const float*)d_in[i];
        else                         Bst = (const float*)d_in[i];
    }
    float* out = (float*)d_out;
    const int K = L / CSZ;   // 64 for L=1024

    const int smem1 = (2 * NDIM * APAD + 2 * NDIM * WCOLS) * (int)sizeof(float); // 212 KB
    cudaFuncSetAttribute(pass1_chunk, cudaFuncAttributeMaxDynamicSharedMemorySize, smem1);

    pass1_chunk<<<dim3(2, K), 512, smem1>>>(A, inp, Bst, out);
    pass2_scan <<<BDIM, 512>>>(out, K);
    pass3_apply<<<L, 256>>>(out);
}

// round 12
// speedup vs baseline: 1.3163x; 1.3163x over previous
#include <cuda_runtime.h>
#include <cuda_bf16.h>
#include <mma.h>
#include <cstdint>

using namespace nvcuda;

// HiPPO-LegS scan:  x_t = A_t x_{t-1} + inputs[t,b] * B_t,  x_{-1} = 0
//   inputs (L,32) f32; A_stacked (L,128,128) f32; B_stacked (L,128) f32
//   out (L,32,128) f32
//
// Pass 1 (wmma/HMMA): per chunk k (16 steps), per 80-column half h, evolve the
//   TRANSPOSED augmented state X (80 aug-cols x 128) via X <- X * A^T using
//   bf16 split-2 (4 MMA terms, fp32 acc). Per step stores P_t (transposed
//   [t][col][i]) to g_P and y_t to out.
// Pass 2: exact fp32 sequential scan over K chunk transitions -> g_S.
// Pass 3: out[t] += P_t * S_k  (f32x2 packed FMA).

#define NDIM 128
#define BDIM 32
#define CSZ  16
#define KMAX 64
#define LMAX 1024
#define XR   80      // augmented columns per block
#define AP   136     // padded leading dim (elements) for A/X/D tiles

typedef unsigned long long ull;

__device__ float g_P[(size_t)LMAX * NDIM * NDIM];   // [t][col][i] = P_t[i][col]
__device__ float g_S[KMAX * BDIM * NDIM];           // [k][b][i] state BEFORE chunk k

// ---- packed fp32x2 helpers --------------------------------------------------
__device__ __forceinline__ ull fma2(ull a, ull b, ull c) {
    ull d;
    asm("fma.rn.f32x2 %0, %1, %2, %3;" : "=l"(d) : "l"(a), "l"(b), "l"(c));
    return d;
}
__device__ __forceinline__ ull pack2(float x, float y) {
    ull d;
    asm("mov.b64 %0, {%1, %2};" : "=l"(d) : "f"(x), "f"(y));
    return d;
}
__device__ __forceinline__ float2 unpack2(ull v) {
    float2 r;
    asm("mov.b64 {%0, %1}, %2;" : "=f"(r.x), "=f"(r.y) : "l"(v));
    return r;
}

// ---- cp.async helpers (sm_80 baseline) --------------------------------------
__device__ __forceinline__ uint32_t smem_u32(const void* p) {
    uint32_t a;
    asm("{ .reg .u64 t; cvta.to.shared.u64 t, %1; cvt.u32.u64 %0, t; }" : "=r"(a) : "l"(p));
    return a;
}
#define CP16(dst, src) \
    asm volatile("cp.async.cg.shared.global [%0], [%1], 16;" :: "r"(dst), "l"(src) : "memory")
#define CP_COMMIT() asm volatile("cp.async.commit_group;" ::: "memory")
#define CP_WAIT0()  asm volatile("cp.async.wait_group 0;" ::: "memory")

// ---------------------------------------------------------------------------
// Pass 1: grid = (2, K), block = 256 (8 warps).  Warp w owns i-tile n0 = 16w.
// SMEM: Ahi/Alo (128 x AP bf16), Xhi/Xlo (80 x AP bf16), Dst (80 x AP f32),
//       Araw (128 x 128 f32, cp.async landing buffer). Total ~217 KB.
// ---------------------------------------------------------------------------
__global__ __launch_bounds__(256, 1)
void pass1_wmma(const float* __restrict__ A, const float* __restrict__ inp,
                const float* __restrict__ Bst, float* __restrict__ outp)
{
    extern __shared__ char smc[];
    __nv_bfloat16* Ahi = reinterpret_cast<__nv_bfloat16*>(smc);
    __nv_bfloat16* Alo = Ahi + NDIM * AP;
    __nv_bfloat16* Xhi = Alo + NDIM * AP;
    __nv_bfloat16* Xlo = Xhi + XR * AP;
    float*         Dst = reinterpret_cast<float*>(Xlo + XR * AP);
    float*         Araw = Dst + XR * AP;

    const int k   = blockIdx.y;
    const int h   = blockIdx.x;
    const int c0  = h * XR;
    const int tid = threadIdx.x;
    const int wid = tid >> 5;

    const uint32_t araw_s = smem_u32(Araw);

    // init X: P columns = identity, y columns = 0 (hi), lo = 0
    for (int idx = tid; idx < XR * NDIM; idx += 256) {
        int c = idx >> 7, j = idx & 127;
        Xhi[c * AP + j] = __float2bfloat16((c0 + c == j) ? 1.0f : 0.0f);
        Xlo[c * AP + j] = __float2bfloat16(0.0f);
    }

    // stage A_{t0}: cp.async -> Araw, then convert to bf16 hi/lo
    {
        const float* Ag = A + (size_t)(k * CSZ) * (NDIM * NDIM);
#pragma unroll
        for (int v = 0; v < 16; ++v) {
            int e = tid + v * 256;                 // 16B chunk id, 0..4095
            CP16(araw_s + e * 16, Ag + e * 4);
        }
        CP_COMMIT(); CP_WAIT0();
#pragma unroll
        for (int v = 0; v < 16; ++v) {
            int e = tid + v * 256;
            int r = e >> 5, c = (e & 31) << 2;
            float4 x = reinterpret_cast<const float4*>(Araw)[e];
            __nv_bfloat162 h0 = __floats2bfloat162_rn(x.x, x.y);
            __nv_bfloat162 h1 = __floats2bfloat162_rn(x.z, x.w);
            float2 f0 = __bfloat1622float2(h0);
            float2 f1 = __bfloat1622float2(h1);
            __nv_bfloat162 l0 = __floats2bfloat162_rn(x.x - f0.x, x.y - f0.y);
            __nv_bfloat162 l1 = __floats2bfloat162_rn(x.z - f1.x, x.w - f1.y);
            *reinterpret_cast<__nv_bfloat162*>(Ahi + r * AP + c)     = h0;
            *reinterpret_cast<__nv_bfloat162*>(Ahi + r * AP + c + 2) = h1;
            *reinterpret_cast<__nv_bfloat162*>(Alo + r * AP + c)     = l0;
            *reinterpret_cast<__nv_bfloat162*>(Alo + r * AP + c + 2) = l1;
        }
    }
    __syncthreads();

    for (int lt = 0; lt < CSZ; ++lt) {
        const int t = k * CSZ + lt;

        // kick off A_{t+1} copy (lands in Araw; consumed at end of this step)
        if (lt + 1 < CSZ) {
            const float* Ag = A + (size_t)(t + 1) * (NDIM * NDIM);
#pragma unroll
            for (int v = 0; v < 16; ++v) {
                int e = tid + v * 256;
                CP16(araw_s + e * 16, Ag + e * 4);
            }
            CP_COMMIT();
        }

        // ---- MMA: D(80 x 128) = X(80 x 128) * A^T  (4 bf16 terms) ----------
        wmma::fragment<wmma::accumulator, 16, 16, 16, float> acc[5];
#pragma unroll
        for (int ct = 0; ct < 5; ++ct) wmma::fill_fragment(acc[ct], 0.0f);

#pragma unroll
        for (int kk = 0; kk < 8; ++kk) {
            wmma::fragment<wmma::matrix_b, 16, 16, 16, __nv_bfloat16, wmma::col_major> bh, bl;
            wmma::load_matrix_sync(bh, Ahi + (size_t)(wid * 16) * AP + kk * 16, AP);
            wmma::load_matrix_sync(bl, Alo + (size_t)(wid * 16) * AP + kk * 16, AP);
#pragma unroll
            for (int ct = 0; ct < 5; ++ct) {
                wmma::fragment<wmma::matrix_a, 16, 16, 16, __nv_bfloat16, wmma::row_major> ah, al;
                wmma::load_matrix_sync(ah, Xhi + (size_t)(ct * 16) * AP + kk * 16, AP);
                wmma::load_matrix_sync(al, Xlo + (size_t)(ct * 16) * AP + kk * 16, AP);
                wmma::mma_sync(acc[ct], ah, bh, acc[ct]);
                wmma::mma_sync(acc[ct], al, bh, acc[ct]);
                wmma::mma_sync(acc[ct], ah, bl, acc[ct]);
                wmma::mma_sync(acc[ct], al, bl, acc[ct]);
            }
        }
#pragma unroll
        for (int ct = 0; ct < 5; ++ct)
            wmma::store_matrix_sync(Dst + (size_t)(ct * 16) * AP + wid * 16,
                                    acc[ct], AP, wmma::mem_row_major);
        __syncthreads();   // all D tiles visible; all X reads done

        // ---- epilogue: D -> (u-inject) -> g_P/out + X_{t+1} split ----------
        for (int idx = tid; idx < XR * NDIM; idx += 256) {
            int c = idx >> 7, i = idx & 127;
            int cg = c0 + c;
            float x = Dst[c * AP + i];
            if (cg >= NDIM)
                x += inp[t * BDIM + (cg - NDIM)] * Bst[t * NDIM + i];
            if (cg < NDIM)
                g_P[((size_t)t * NDIM + cg) * NDIM + i] = x;
            else
                outp[(size_t)t * (BDIM * NDIM) + (size_t)(cg - NDIM) * NDIM + i] = x;
            if (lt + 1 < CSZ) {
                __nv_bfloat16 hv = __float2bfloat16(x);
                Xhi[c * AP + i] = hv;
                Xlo[c * AP + i] = __float2bfloat16(x - __bfloat162float(hv));
            }
        }

        // ---- convert A_{t+1} (own chunks only; no cross-thread dep) --------
        if (lt + 1 < CSZ) {
            CP_WAIT0();
#pragma unroll
            for (int v = 0; v < 16; ++v) {
                int e = tid + v * 256;
                int r = e >> 5, c = (e & 31) << 2;
                float4 x = reinterpret_cast<const float4*>(Araw)[e];
                __nv_bfloat162 h0 = __floats2bfloat162_rn(x.x, x.y);
                __nv_bfloat162 h1 = __floats2bfloat162_rn(x.z, x.w);
                float2 f0 = __bfloat1622float2(h0);
                float2 f1 = __bfloat1622float2(h1);
                __nv_bfloat162 l0 = __floats2bfloat162_rn(x.x - f0.x, x.y - f0.y);
                __nv_bfloat162 l1 = __floats2bfloat162_rn(x.z - f1.x, x.w - f1.y);
                *reinterpret_cast<__nv_bfloat162*>(Ahi + r * AP + c)     = h0;
                *reinterpret_cast<__nv_bfloat162*>(Ahi + r * AP + c + 2) = h1;
                *reinterpret_cast<__nv_bfloat162*>(Alo + r * AP + c)     = l0;
                *reinterpret_cast<__nv_bfloat162*>(Alo + r * AP + c + 2) = l1;
            }
        }
        __syncthreads();   // X_{t+1} + A_{t+1} ready
    }
}

// ---------------------------------------------------------------------------
// Pass 2: exact fp32 sequential scan over chunk transitions; one block per
// batch column. grid = 32, block = 512, M/v register-prefetched one iter ahead.
// ---------------------------------------------------------------------------
__global__ __launch_bounds__(512, 1)
void pass2_scan(const float* __restrict__ outy, int K)
{
    __shared__ float s[NDIM];
    __shared__ float part[16 * NDIM];
    const int b   = blockIdx.x;
    const int tid = threadIdx.x;
    const int i0  = (tid & 31) << 2;
    const int q   = tid >> 5;
    const int j0  = q << 3;

    if (tid < NDIM) s[tid] = 0.0f;

    float4 mbuf[8];
    {
        const float* M0 = g_P + ((size_t)(CSZ - 1)) * (NDIM * NDIM);
#pragma unroll
        for (int jj = 0; jj < 8; ++jj)
            mbuf[jj] = *reinterpret_cast<const float4*>(M0 + (j0 + jj) * NDIM + i0);
    }
    float vreg = (tid < NDIM)
        ? outy[((size_t)(CSZ - 1)) * (BDIM * NDIM) + b * NDIM + tid] : 0.0f;
    __syncthreads();

    for (int k = 0; k < K; ++k) {
        if (tid < NDIM)
            g_S[k * (BDIM * NDIM) + b * NDIM + tid] = s[tid];

        const int kn = (k + 1 < K) ? (k + 1) : k;
        const float* Mn = g_P + ((size_t)(kn * CSZ + CSZ - 1)) * (NDIM * NDIM);
        float4 nbuf[8];
#pragma unroll
        for (int jj = 0; jj < 8; ++jj)
            nbuf[jj] = *reinterpret_cast<const float4*>(Mn + (j0 + jj) * NDIM + i0);
        float vn = (tid < NDIM)
            ? outy[((size_t)(kn * CSZ + CSZ - 1)) * (BDIM * NDIM) + b * NDIM + tid] : 0.0f;

        float4 acc = make_float4(0.f, 0.f, 0.f, 0.f);
#pragma unroll
        for (int jj = 0; jj < 8; ++jj) {
            float sj = s[j0 + jj];
            acc.x += mbuf[jj].x * sj; acc.y += mbuf[jj].y * sj;
            acc.z += mbuf[jj].z * sj; acc.w += mbuf[jj].w * sj;
        }
        *reinterpret_cast<float4*>(&part[q * NDIM + i0]) = acc;
        __syncthreads();

        if (tid < NDIM) {
            float r = vreg;
#pragma unroll
            for (int qq = 0; qq < 16; ++qq) r += part[qq * NDIM + tid];
            s[tid] = r;
        }
#pragma unroll
        for (int jj = 0; jj < 8; ++jj) mbuf[jj] = nbuf[jj];
        vreg = vn;
        __syncthreads();
    }
}

// ---------------------------------------------------------------------------
// Pass 3: out[t][b][i] += sum_j P_t[i][j] * S_k[b][j].  grid = L, block = 256.
// Inner loop uses packed f32x2 FMA (sS reads are warp-broadcast).
// ---------------------------------------------------------------------------
__global__ __launch_bounds__(256, 1)
void pass3_apply(float* __restrict__ outp)
{
    __shared__ float sS[NDIM * 36];      // [j*36 + b]
    const int t   = blockIdx.x;
    const int k   = t >> 4;
    const int tid = threadIdx.x;

    for (int idx = tid; idx < NDIM * BDIM; idx += 256) {
        int b = idx >> 7, j = idx & 127;
        sS[j * 36 + b] = g_S[k * (BDIM * NDIM) + idx];
    }
    __syncthreads();

    const int i  = tid & 127;
    const int b0 = (tid >> 7) << 4;      // 0 or 16
    const size_t obase = (size_t)t * (BDIM * NDIM);

    ull acc[8];
#pragma unroll
    for (int q = 0; q < 8; ++q)
        acc[q] = pack2(outp[obase + (b0 + 2 * q) * NDIM + i],
                       outp[obase + (b0 + 2 * q + 1) * NDIM + i]);

    const float* P = g_P + (size_t)t * (NDIM * NDIM);
#pragma unroll 4
    for (int j = 0; j < NDIM; ++j) {
        float p = P[j * NDIM + i];
        ull pp = pack2(p, p);
        const ull* sp = reinterpret_cast<const ull*>(&sS[j * 36 + b0]);
#pragma unroll
        for (int q = 0; q < 8; ++q)
            acc[q] = fma2(pp, sp[q], acc[q]);
    }

#pragma unroll
    for (int q = 0; q < 8; ++q) {
        float2 r = unpack2(acc[q]);
        outp[obase + (b0 + 2 * q) * NDIM + i]     = r.x;
        outp[obase + (b0 + 2 * q + 1) * NDIM + i] = r.y;
    }
}

// ---------------------------------------------------------------------------
extern "C" void kernel_launch(void* const* d_in, const int* in_sizes, int n_in,
                              void* d_out, int out_size)
{
    int ia = 0;
    for (int i = 1; i < n_in; ++i)
        if (in_sizes[i] > in_sizes[ia]) ia = i;
    const float* A = (const float*)d_in[ia];
    const int L = in_sizes[ia] / (NDIM * NDIM);
    const float* inp = nullptr;
    const float* Bst = nullptr;
    for (int i = 0; i < n_in; ++i) {
        if (i == ia) continue;
        if (in_sizes[i] == L * BDIM) inp = (const float*)d_in[i];
        else                         Bst = (const float*)d_in[i];
    }
    float* out = (float*)d_out;
    const int K = L / CSZ;

    // smem: Ahi+Alo (2*128*AP*2B) + Xhi+Xlo (2*80*AP*2B) + Dst (80*AP*4B) + Araw (64KB)
    const int smem1 = (2 * NDIM * AP * 2) + (2 * XR * AP * 2) + (XR * AP * 4)
                    + (NDIM * NDIM * 4);
    cudaFuncSetAttribute(pass1_wmma, cudaFuncAttributeMaxDynamicSharedMemorySize, smem1);

    pass1_wmma<<<dim3(2, K), 256, smem1>>>(A, inp, Bst, out);
    pass2_scan<<<BDIM, 512>>>(out, K);
    pass3_apply<<<L, 256>>>(out);
}

// round 14
// speedup vs baseline: 1.4898x; 1.1318x over previous
#include <cuda_runtime.h>
#include <cuda_bf16.h>
#include <mma.h>
#include <cstdint>

using namespace nvcuda;

// HiPPO-LegS scan:  x_t = A_t x_{t-1} + inputs[t,b] * B_t,  x_{-1} = 0
//   inputs (L,32) f32; A_stacked (L,128,128) f32; B_stacked (L,128) f32
//   out (L,32,128) f32
//
// Pass 1 (wmma/HMMA): per chunk k (16 steps), per 80-column half h, evolve the
//   TRANSPOSED augmented state X (80 aug-cols x 128) via X <- X * A^T using
//   bf16 split-2 (3 MMA terms: AhBh + AlBh + AhBl, fp32 acc). Per step stores
//   P_t (transposed [t][col][i]) to g_P and y_t to out.
// Pass 2: exact fp32 sequential scan over K chunk transitions -> g_S
//   (register prefetch distance 2 to cover DRAM latency).
// Pass 3: out[t] += P_t * S_k  (f32x2 packed FMA).

#define NDIM 128
#define BDIM 32
#define CSZ  16
#define KMAX 64
#define LMAX 1024
#define XR   80      // augmented columns per block
#define AP   136     // padded leading dim (elements) for A/X/D tiles

typedef unsigned long long ull;

__device__ float g_P[(size_t)LMAX * NDIM * NDIM];   // [t][col][i] = P_t[i][col]
__device__ float g_S[KMAX * BDIM * NDIM];           // [k][b][i] state BEFORE chunk k

// ---- packed fp32x2 helpers --------------------------------------------------
__device__ __forceinline__ ull fma2(ull a, ull b, ull c) {
    ull d;
    asm("fma.rn.f32x2 %0, %1, %2, %3;" : "=l"(d) : "l"(a), "l"(b), "l"(c));
    return d;
}
__device__ __forceinline__ ull pack2(float x, float y) {
    ull d;
    asm("mov.b64 %0, {%1, %2};" : "=l"(d) : "f"(x), "f"(y));
    return d;
}
__device__ __forceinline__ float2 unpack2(ull v) {
    float2 r;
    asm("mov.b64 {%0, %1}, %2;" : "=f"(r.x), "=f"(r.y) : "l"(v));
    return r;
}

// ---- cp.async helpers (sm_80 baseline) --------------------------------------
__device__ __forceinline__ uint32_t smem_u32(const void* p) {
    uint32_t a;
    asm("{ .reg .u64 t; cvta.to.shared.u64 t, %1; cvt.u32.u64 %0, t; }" : "=r"(a) : "l"(p));
    return a;
}
#define CP16(dst, src) \
    asm volatile("cp.async.cg.shared.global [%0], [%1], 16;" :: "r"(dst), "l"(src) : "memory")
#define CP_COMMIT() asm volatile("cp.async.commit_group;" ::: "memory")
#define CP_WAIT0()  asm volatile("cp.async.wait_group 0;" ::: "memory")

// ---------------------------------------------------------------------------
// Pass 1: grid = (2, K), block = 512 (16 warps).
// Warp w: wn = w&7 owns i-tile (16 cols of i), wc = w>>3 owns ct tiles
// {0,1,2} (wc=0) or {3,4} (wc=1). Per SMSP: 2 warps of each kind (balanced).
// SMEM: Ahi/Alo (128 x AP bf16), Xhi/Xlo (80 x AP bf16), Dst (80 x AP f32),
//       Araw (128 x 128 f32 cp.async landing buffer). Total ~217 KB.
// ---------------------------------------------------------------------------
__global__ __launch_bounds__(512, 1)
void pass1_wmma(const float* __restrict__ A, const float* __restrict__ inp,
                const float* __restrict__ Bst, float* __restrict__ outp)
{
    extern __shared__ char smc[];
    __nv_bfloat16* Ahi = reinterpret_cast<__nv_bfloat16*>(smc);
    __nv_bfloat16* Alo = Ahi + NDIM * AP;
    __nv_bfloat16* Xhi = Alo + NDIM * AP;
    __nv_bfloat16* Xlo = Xhi + XR * AP;
    float*         Dst = reinterpret_cast<float*>(Xlo + XR * AP);
    float*         Araw = Dst + XR * AP;

    const int k   = blockIdx.y;
    const int h   = blockIdx.x;
    const int c0  = h * XR;
    const int tid = threadIdx.x;
    const int wid = tid >> 5;
    const int wn  = wid & 7;         // i-tile
    const int wc  = wid >> 3;        // ct group: 0 -> {0,1,2}, 1 -> {3,4}
    const int ct0 = wc ? 3 : 0;
    const int nct = wc ? 2 : 3;

    const uint32_t araw_s = smem_u32(Araw);

    // init X: P columns = identity, y columns = 0 (hi), lo = 0
    for (int idx = tid; idx < XR * NDIM; idx += 512) {
        int c = idx >> 7, j = idx & 127;
        Xhi[c * AP + j] = __float2bfloat16((c0 + c == j) ? 1.0f : 0.0f);
        Xlo[c * AP + j] = __float2bfloat16(0.0f);
    }

    // stage A_{t0}: cp.async -> Araw, then convert to bf16 hi/lo
    {
        const float* Ag = A + (size_t)(k * CSZ) * (NDIM * NDIM);
#pragma unroll
        for (int v = 0; v < 8; ++v) {
            int e = tid + v * 512;                 // 16B chunk id, 0..4095
            CP16(araw_s + e * 16, Ag + e * 4);
        }
        CP_COMMIT(); CP_WAIT0();
        __syncthreads();
#pragma unroll
        for (int v = 0; v < 8; ++v) {
            int e = tid + v * 512;
            int r = e >> 5, c = (e & 31) << 2;
            float4 x = reinterpret_cast<const float4*>(Araw)[e];
            __nv_bfloat162 h0 = __floats2bfloat162_rn(x.x, x.y);
            __nv_bfloat162 h1 = __floats2bfloat162_rn(x.z, x.w);
            float2 f0 = __bfloat1622float2(h0);
            float2 f1 = __bfloat1622float2(h1);
            __nv_bfloat162 l0 = __floats2bfloat162_rn(x.x - f0.x, x.y - f0.y);
            __nv_bfloat162 l1 = __floats2bfloat162_rn(x.z - f1.x, x.w - f1.y);
            *reinterpret_cast<__nv_bfloat162*>(Ahi + r * AP + c)     = h0;
            *reinterpret_cast<__nv_bfloat162*>(Ahi + r * AP + c + 2) = h1;
            *reinterpret_cast<__nv_bfloat162*>(Alo + r * AP + c)     = l0;
            *reinterpret_cast<__nv_bfloat162*>(Alo + r * AP + c + 2) = l1;
        }
    }
    __syncthreads();

    for (int lt = 0; lt < CSZ; ++lt) {
        const int t = k * CSZ + lt;

        // kick off A_{t+1} copy (lands in Araw; consumed at end of this step)
        if (lt + 1 < CSZ) {
            const float* Ag = A + (size_t)(t + 1) * (NDIM * NDIM);
#pragma unroll
            for (int v = 0; v < 8; ++v) {
                int e = tid + v * 512;
                CP16(araw_s + e * 16, Ag + e * 4);
            }
            CP_COMMIT();
        }

        // ---- MMA: D(80 x 128) = X(80 x 128) * A^T  (3 bf16 terms) ----------
        wmma::fragment<wmma::accumulator, 16, 16, 16, float> acc[3];
#pragma unroll
        for (int c = 0; c < 3; ++c)
            if (c < nct) wmma::fill_fragment(acc[c], 0.0f);

#pragma unroll
        for (int kk = 0; kk < 8; ++kk) {
            wmma::fragment<wmma::matrix_b, 16, 16, 16, __nv_bfloat16, wmma::col_major> bh, bl;
            wmma::load_matrix_sync(bh, Ahi + (size_t)(wn * 16) * AP + kk * 16, AP);
            wmma::load_matrix_sync(bl, Alo + (size_t)(wn * 16) * AP + kk * 16, AP);
#pragma unroll
            for (int c = 0; c < 3; ++c) {
                if (c < nct) {
                    const int ct = ct0 + c;
                    wmma::fragment<wmma::matrix_a, 16, 16, 16, __nv_bfloat16, wmma::row_major> ah, al;
                    wmma::load_matrix_sync(ah, Xhi + (size_t)(ct * 16) * AP + kk * 16, AP);
                    wmma::load_matrix_sync(al, Xlo + (size_t)(ct * 16) * AP + kk * 16, AP);
                    wmma::mma_sync(acc[c], ah, bh, acc[c]);
                    wmma::mma_sync(acc[c], al, bh, acc[c]);
                    wmma::mma_sync(acc[c], ah, bl, acc[c]);
                }
            }
        }
#pragma unroll
        for (int c = 0; c < 3; ++c)
            if (c < nct)
                wmma::store_matrix_sync(Dst + (size_t)((ct0 + c) * 16) * AP + wn * 16,
                                        acc[c], AP, wmma::mem_row_major);
        __syncthreads();   // all D tiles visible; all X reads done

        // ---- epilogue: D -> (u-inject) -> g_P/out + X_{t+1} split ----------
        for (int idx = tid; idx < XR * NDIM; idx += 512) {
            int c = idx >> 7, i = idx & 127;
            int cg = c0 + c;
            float x = Dst[c * AP + i];
            if (cg >= NDIM)
                x += inp[t * BDIM + (cg - NDIM)] * Bst[t * NDIM + i];
            if (cg < NDIM)
                g_P[((size_t)t * NDIM + cg) * NDIM + i] = x;
            else
                outp[(size_t)t * (BDIM * NDIM) + (size_t)(cg - NDIM) * NDIM + i] = x;
            if (lt + 1 < CSZ) {
                __nv_bfloat16 hv = __float2bfloat16(x);
                Xhi[c * AP + i] = hv;
                Xlo[c * AP + i] = __float2bfloat16(x - __bfloat162float(hv));
            }
        }

        // ---- convert A_{t+1} (own chunks only; no cross-thread dep) --------
        if (lt + 1 < CSZ) {
            CP_WAIT0();
#pragma unroll
            for (int v = 0; v < 8; ++v) {
                int e = tid + v * 512;
                int r = e >> 5, c = (e & 31) << 2;
                float4 x = reinterpret_cast<const float4*>(Araw)[e];
                __nv_bfloat162 h0 = __floats2bfloat162_rn(x.x, x.y);
                __nv_bfloat162 h1 = __floats2bfloat162_rn(x.z, x.w);
                float2 f0 = __bfloat1622float2(h0);
                float2 f1 = __bfloat1622float2(h1);
                __nv_bfloat162 l0 = __floats2bfloat162_rn(x.x - f0.x, x.y - f0.y);
                __nv_bfloat162 l1 = __floats2bfloat162_rn(x.z - f1.x, x.w - f1.y);
                *reinterpret_cast<__nv_bfloat162*>(Ahi + r * AP + c)     = h0;
                *reinterpret_cast<__nv_bfloat162*>(Ahi + r * AP + c + 2) = h1;
                *reinterpret_cast<__nv_bfloat162*>(Alo + r * AP + c)     = l0;
                *reinterpret_cast<__nv_bfloat162*>(Alo + r * AP + c + 2) = l1;
            }
        }
        __syncthreads();   // X_{t+1} + A_{t+1} ready
    }
}

// ---------------------------------------------------------------------------
// Pass 2: exact fp32 sequential scan over chunk transitions; one block per
// batch column. grid = 32, block = 512. Register prefetch DISTANCE 2: loads
// for chunk k+2 are issued at iteration k, giving a ~2-iteration window to
// cover DRAM latency on M / v reads.
// ---------------------------------------------------------------------------
__global__ __launch_bounds__(512, 1)
void pass2_scan(const float* __restrict__ outy, int K)
{
    __shared__ float s[NDIM];
    __shared__ float part[16 * NDIM];
    const int b   = blockIdx.x;
    const int tid = threadIdx.x;
    const int i0  = (tid & 31) << 2;
    const int q   = tid >> 5;
    const int j0  = q << 3;

    if (tid < NDIM) s[tid] = 0.0f;

    // preload k=0 and k=1
    float4 mbuf[8], nbuf[8];
    float vreg, vn;
    {
        const float* M0 = g_P + ((size_t)(CSZ - 1)) * (NDIM * NDIM);
#pragma unroll
        for (int jj = 0; jj < 8; ++jj)
            mbuf[jj] = *reinterpret_cast<const float4*>(M0 + (j0 + jj) * NDIM + i0);
        vreg = (tid < NDIM)
            ? outy[((size_t)(CSZ - 1)) * (BDIM * NDIM) + b * NDIM + tid] : 0.0f;

        const int k1 = (1 < K) ? 1 : 0;
        const float* M1 = g_P + ((size_t)(k1 * CSZ + CSZ - 1)) * (NDIM * NDIM);
#pragma unroll
        for (int jj = 0; jj < 8; ++jj)
            nbuf[jj] = *reinterpret_cast<const float4*>(M1 + (j0 + jj) * NDIM + i0);
        vn = (tid < NDIM)
            ? outy[((size_t)(k1 * CSZ + CSZ - 1)) * (BDIM * NDIM) + b * NDIM + tid] : 0.0f;
    }
    __syncthreads();

    for (int k = 0; k < K; ++k) {
        if (tid < NDIM)
            g_S[k * (BDIM * NDIM) + b * NDIM + tid] = s[tid];

        // issue loads for k+2 (independent of carried state s)
        const int k2 = (k + 2 < K) ? (k + 2) : (K - 1);
        const float* M2 = g_P + ((size_t)(k2 * CSZ + CSZ - 1)) * (NDIM * NDIM);
        float4 n2buf[8];
#pragma unroll
        for (int jj = 0; jj < 8; ++jj)
            n2buf[jj] = *reinterpret_cast<const float4*>(M2 + (j0 + jj) * NDIM + i0);
        float v2 = (tid < NDIM)
            ? outy[((size_t)(k2 * CSZ + CSZ - 1)) * (BDIM * NDIM) + b * NDIM + tid] : 0.0f;

        float4 acc = make_float4(0.f, 0.f, 0.f, 0.f);
#pragma unroll
        for (int jj = 0; jj < 8; ++jj) {
            float sj = s[j0 + jj];
            acc.x += mbuf[jj].x * sj; acc.y += mbuf[jj].y * sj;
            acc.z += mbuf[jj].z * sj; acc.w += mbuf[jj].w * sj;
        }
        *reinterpret_cast<float4*>(&part[q * NDIM + i0]) = acc;
        __syncthreads();

        if (tid < NDIM) {
            float r = vreg;
#pragma unroll
            for (int qq = 0; qq < 16; ++qq) r += part[qq * NDIM + tid];
            s[tid] = r;
        }
#pragma unroll
        for (int jj = 0; jj < 8; ++jj) { mbuf[jj] = nbuf[jj]; nbuf[jj] = n2buf[jj]; }
        vreg = vn; vn = v2;
        __syncthreads();
    }
}

// ---------------------------------------------------------------------------
// Pass 3: out[t][b][i] += sum_j P_t[i][j] * S_k[b][j].  grid = L, block = 256.
// Inner loop uses packed f32x2 FMA (sS reads are warp-broadcast).
// ---------------------------------------------------------------------------
__global__ __launch_bounds__(256, 1)
void pass3_apply(float* __restrict__ outp)
{
    __shared__ float sS[NDIM * 36];      // [j*36 + b]
    const int t   = blockIdx.x;
    const int k   = t >> 4;
    const int tid = threadIdx.x;

    for (int idx = tid; idx < NDIM * BDIM; idx += 256) {
        int b = idx >> 7, j = idx & 127;
        sS[j * 36 + b] = g_S[k * (BDIM * NDIM) + idx];
    }
    __syncthreads();

    const int i  = tid & 127;
    const int b0 = (tid >> 7) << 4;      // 0 or 16
    const size_t obase = (size_t)t * (BDIM * NDIM);

    ull acc[8];
#pragma unroll
    for (int q = 0; q < 8; ++q)
        acc[q] = pack2(outp[obase + (b0 + 2 * q) * NDIM + i],
                       outp[obase + (b0 + 2 * q + 1) * NDIM + i]);

    const float* P = g_P + (size_t)t * (NDIM * NDIM);
#pragma unroll 4
    for (int j = 0; j < NDIM; ++j) {
        float p = P[j * NDIM + i];
        ull pp = pack2(p, p);
        const ull* sp = reinterpret_cast<const ull*>(&sS[j * 36 + b0]);
#pragma unroll
        for (int q = 0; q < 8; ++q)
            acc[q] = fma2(pp, sp[q], acc[q]);
    }

#pragma unroll
    for (int q = 0; q < 8; ++q) {
        float2 r = unpack2(acc[q]);
        outp[obase + (b0 + 2 * q) * NDIM + i]     = r.x;
        outp[obase + (b0 + 2 * q + 1) * NDIM + i] = r.y;
    }
}

// ---------------------------------------------------------------------------
extern "C" void kernel_launch(void* const* d_in, const int* in_sizes, int n_in,
                              void* d_out, int out_size)
{
    int ia = 0;
    for (int i = 1; i < n_in; ++i)
        if (in_sizes[i] > in_sizes[ia]) ia = i;
    const float* A = (const float*)d_in[ia];
    const int L = in_sizes[ia] / (NDIM * NDIM);
    const float* inp = nullptr;
    const float* Bst = nullptr;
    for (int i = 0; i < n_in; ++i) {
        if (i == ia) continue;
        if (in_sizes[i] == L * BDIM) inp = (const float*)d_in[i];
        else                         Bst = (const float*)d_in[i];
    }
    float* out = (float*)d_out;
    const int K = L / CSZ;

    // smem: Ahi+Alo + Xhi+Xlo + Dst + Araw  (~217 KB)
    const int smem1 = (2 * NDIM * AP * 2) + (2 * XR * AP * 2) + (XR * AP * 4)
                    + (NDIM * NDIM * 4);
    cudaFuncSetAttribute(pass1_wmma, cudaFuncAttributeMaxDynamicSharedMemorySize, smem1);

    pass1_wmma<<<dim3(2, K), 512, smem1>>>(A, inp, Bst, out);
    pass2_scan<<<BDIM, 512>>>(out, K);
    pass3_apply<<<L, 256>>>(out);
}

// round 15
// speedup vs baseline: 1.4905x; 1.0004x over previous
#include <cuda_runtime.h>
#include <cuda_bf16.h>
#include <mma.h>
#include <cstdint>

using namespace nvcuda;

// HiPPO-LegS scan:  x_t = A_t x_{t-1} + inputs[t,b] * B_t,  x_{-1} = 0
//   inputs (L,32) f32; A_stacked (L,128,128) f32; B_stacked (L,128) f32
//   out (L,32,128) f32
//
// Pass 1 (wmma/HMMA): per chunk k (16 steps), per 80-column half h, evolve the
//   TRANSPOSED augmented state X (80 aug-cols x 128) via X <- X * A^T using
//   bf16 split-2 (3 MMA terms, fp32 acc). Per step stores P_t to g_P, y_t to out.
// Pass 2: exact fp32 sequential scan over K chunk transitions -> g_S.
//   Unroll-2 register double-buffering: loads for k+2 issued at k with NO
//   register copies, giving a ~2-iteration latency window.
// Pass 3: out[t] += P_t * S_k  (f32x2 packed FMA).

#define NDIM 128
#define BDIM 32
#define CSZ  16
#define KMAX 64
#define LMAX 1024
#define XR   80      // augmented columns per block
#define AP   136     // padded leading dim (elements) for A/X/D tiles

typedef unsigned long long ull;

__device__ float g_P[(size_t)LMAX * NDIM * NDIM];   // [t][col][i] = P_t[i][col]
__device__ float g_S[KMAX * BDIM * NDIM];           // [k][b][i] state BEFORE chunk k

// ---- packed fp32x2 helpers --------------------------------------------------
__device__ __forceinline__ ull fma2(ull a, ull b, ull c) {
    ull d;
    asm("fma.rn.f32x2 %0, %1, %2, %3;" : "=l"(d) : "l"(a), "l"(b), "l"(c));
    return d;
}
__device__ __forceinline__ ull pack2(float x, float y) {
    ull d;
    asm("mov.b64 %0, {%1, %2};" : "=l"(d) : "f"(x), "f"(y));
    return d;
}
__device__ __forceinline__ float2 unpack2(ull v) {
    float2 r;
    asm("mov.b64 {%0, %1}, %2;" : "=f"(r.x), "=f"(r.y) : "l"(v));
    return r;
}

// ---- cp.async helpers (sm_80 baseline) --------------------------------------
__device__ __forceinline__ uint32_t smem_u32(const void* p) {
    uint32_t a;
    asm("{ .reg .u64 t; cvta.to.shared.u64 t, %1; cvt.u32.u64 %0, t; }" : "=r"(a) : "l"(p));
    return a;
}
#define CP16(dst, src) \
    asm volatile("cp.async.cg.shared.global [%0], [%1], 16;" :: "r"(dst), "l"(src) : "memory")
#define CP_COMMIT() asm volatile("cp.async.commit_group;" ::: "memory")
#define CP_WAIT0()  asm volatile("cp.async.wait_group 0;" ::: "memory")

// ---------------------------------------------------------------------------
// Pass 1: grid = (2, K), block = 512 (16 warps). (unchanged from R14)
// ---------------------------------------------------------------------------
__global__ __launch_bounds__(512, 1)
void pass1_wmma(const float* __restrict__ A, const float* __restrict__ inp,
                const float* __restrict__ Bst, float* __restrict__ outp)
{
    extern __shared__ char smc[];
    __nv_bfloat16* Ahi = reinterpret_cast<__nv_bfloat16*>(smc);
    __nv_bfloat16* Alo = Ahi + NDIM * AP;
    __nv_bfloat16* Xhi = Alo + NDIM * AP;
    __nv_bfloat16* Xlo = Xhi + XR * AP;
    float*         Dst = reinterpret_cast<float*>(Xlo + XR * AP);
    float*         Araw = Dst + XR * AP;

    const int k   = blockIdx.y;
    const int h   = blockIdx.x;
    const int c0  = h * XR;
    const int tid = threadIdx.x;
    const int wid = tid >> 5;
    const int wn  = wid & 7;         // i-tile
    const int wc  = wid >> 3;        // ct group: 0 -> {0,1,2}, 1 -> {3,4}
    const int ct0 = wc ? 3 : 0;
    const int nct = wc ? 2 : 3;

    const uint32_t araw_s = smem_u32(Araw);

    for (int idx = tid; idx < XR * NDIM; idx += 512) {
        int c = idx >> 7, j = idx & 127;
        Xhi[c * AP + j] = __float2bfloat16((c0 + c == j) ? 1.0f : 0.0f);
        Xlo[c * AP + j] = __float2bfloat16(0.0f);
    }

    {
        const float* Ag = A + (size_t)(k * CSZ) * (NDIM * NDIM);
#pragma unroll
        for (int v = 0; v < 8; ++v) {
            int e = tid + v * 512;
            CP16(araw_s + e * 16, Ag + e * 4);
        }
        CP_COMMIT(); CP_WAIT0();
        __syncthreads();
#pragma unroll
        for (int v = 0; v < 8; ++v) {
            int e = tid + v * 512;
            int r = e >> 5, c = (e & 31) << 2;
            float4 x = reinterpret_cast<const float4*>(Araw)[e];
            __nv_bfloat162 h0 = __floats2bfloat162_rn(x.x, x.y);
            __nv_bfloat162 h1 = __floats2bfloat162_rn(x.z, x.w);
            float2 f0 = __bfloat1622float2(h0);
            float2 f1 = __bfloat1622float2(h1);
            __nv_bfloat162 l0 = __floats2bfloat162_rn(x.x - f0.x, x.y - f0.y);
            __nv_bfloat162 l1 = __floats2bfloat162_rn(x.z - f1.x, x.w - f1.y);
            *reinterpret_cast<__nv_bfloat162*>(Ahi + r * AP + c)     = h0;
            *reinterpret_cast<__nv_bfloat162*>(Ahi + r * AP + c + 2) = h1;
            *reinterpret_cast<__nv_bfloat162*>(Alo + r * AP + c)     = l0;
            *reinterpret_cast<__nv_bfloat162*>(Alo + r * AP + c + 2) = l1;
        }
    }
    __syncthreads();

    for (int lt = 0; lt < CSZ; ++lt) {
        const int t = k * CSZ + lt;

        if (lt + 1 < CSZ) {
            const float* Ag = A + (size_t)(t + 1) * (NDIM * NDIM);
#pragma unroll
            for (int v = 0; v < 8; ++v) {
                int e = tid + v * 512;
                CP16(araw_s + e * 16, Ag + e * 4);
            }
            CP_COMMIT();
        }

        wmma::fragment<wmma::accumulator, 16, 16, 16, float> acc[3];
#pragma unroll
        for (int c = 0; c < 3; ++c)
            if (c < nct) wmma::fill_fragment(acc[c], 0.0f);

#pragma unroll
        for (int kk = 0; kk < 8; ++kk) {
            wmma::fragment<wmma::matrix_b, 16, 16, 16, __nv_bfloat16, wmma::col_major> bh, bl;
            wmma::load_matrix_sync(bh, Ahi + (size_t)(wn * 16) * AP + kk * 16, AP);
            wmma::load_matrix_sync(bl, Alo + (size_t)(wn * 16) * AP + kk * 16, AP);
#pragma unroll
            for (int c = 0; c < 3; ++c) {
                if (c < nct) {
                    const int ct = ct0 + c;
                    wmma::fragment<wmma::matrix_a, 16, 16, 16, __nv_bfloat16, wmma::row_major> ah, al;
                    wmma::load_matrix_sync(ah, Xhi + (size_t)(ct * 16) * AP + kk * 16, AP);
                    wmma::load_matrix_sync(al, Xlo + (size_t)(ct * 16) * AP + kk * 16, AP);
                    wmma::mma_sync(acc[c], ah, bh, acc[c]);
                    wmma::mma_sync(acc[c], al, bh, acc[c]);
                    wmma::mma_sync(acc[c], ah, bl, acc[c]);
                }
            }
        }
#pragma unroll
        for (int c = 0; c < 3; ++c)
            if (c < nct)
                wmma::store_matrix_sync(Dst + (size_t)((ct0 + c) * 16) * AP + wn * 16,
                                        acc[c], AP, wmma::mem_row_major);
        __syncthreads();

        for (int idx = tid; idx < XR * NDIM; idx += 512) {
            int c = idx >> 7, i = idx & 127;
            int cg = c0 + c;
            float x = Dst[c * AP + i];
            if (cg >= NDIM)
                x += inp[t * BDIM + (cg - NDIM)] * Bst[t * NDIM + i];
            if (cg < NDIM)
                g_P[((size_t)t * NDIM + cg) * NDIM + i] = x;
            else
                outp[(size_t)t * (BDIM * NDIM) + (size_t)(cg - NDIM) * NDIM + i] = x;
            if (lt + 1 < CSZ) {
                __nv_bfloat16 hv = __float2bfloat16(x);
                Xhi[c * AP + i] = hv;
                Xlo[c * AP + i] = __float2bfloat16(x - __bfloat162float(hv));
            }
        }

        if (lt + 1 < CSZ) {
            CP_WAIT0();
#pragma unroll
            for (int v = 0; v < 8; ++v) {
                int e = tid + v * 512;
                int r = e >> 5, c = (e & 31) << 2;
                float4 x = reinterpret_cast<const float4*>(Araw)[e];
                __nv_bfloat162 h0 = __floats2bfloat162_rn(x.x, x.y);
                __nv_bfloat162 h1 = __floats2bfloat162_rn(x.z, x.w);
                float2 f0 = __bfloat1622float2(h0);
                float2 f1 = __bfloat1622float2(h1);
                __nv_bfloat162 l0 = __floats2bfloat162_rn(x.x - f0.x, x.y - f0.y);
                __nv_bfloat162 l1 = __floats2bfloat162_rn(x.z - f1.x, x.w - f1.y);
                *reinterpret_cast<__nv_bfloat162*>(Ahi + r * AP + c)     = h0;
                *reinterpret_cast<__nv_bfloat162*>(Ahi + r * AP + c + 2) = h1;
                *reinterpret_cast<__nv_bfloat162*>(Alo + r * AP + c)     = l0;
                *reinterpret_cast<__nv_bfloat162*>(Alo + r * AP + c + 2) = l1;
            }
        }
        __syncthreads();
    }
}

// ---------------------------------------------------------------------------
// Pass 2: exact fp32 sequential scan; one block per batch column.
// grid = 32, block = 512. Unroll-2, two register buffer sets, NO copies:
// step k consumes bufA and re-issues bufA's loads for k+2 right after its
// FMA reads; step k+1 does the same with bufB. True ~2-iteration window.
// ---------------------------------------------------------------------------
__global__ __launch_bounds__(512, 1)
void pass2_scan(const float* __restrict__ outy, int K)
{
    __shared__ float s[NDIM];
    __shared__ float part[16 * NDIM];
    const int b   = blockIdx.x;
    const int tid = threadIdx.x;
    const int i0  = (tid & 31) << 2;
    const int q   = tid >> 5;
    const int j0  = q << 3;

    if (tid < NDIM) s[tid] = 0.0f;

    float4 mbA[8], mbB[8];
    float vA, vB;
    {
        const float* M0 = g_P + ((size_t)(CSZ - 1)) * (NDIM * NDIM);
#pragma unroll
        for (int jj = 0; jj < 8; ++jj)
            mbA[jj] = *reinterpret_cast<const float4*>(M0 + (j0 + jj) * NDIM + i0);
        vA = (tid < NDIM)
            ? outy[((size_t)(CSZ - 1)) * (BDIM * NDIM) + b * NDIM + tid] : 0.0f;

        const int k1 = (1 < K) ? 1 : 0;
        const float* M1 = g_P + ((size_t)(k1 * CSZ + CSZ - 1)) * (NDIM * NDIM);
#pragma unroll
        for (int jj = 0; jj < 8; ++jj)
            mbB[jj] = *reinterpret_cast<const float4*>(M1 + (j0 + jj) * NDIM + i0);
        vB = (tid < NDIM)
            ? outy[((size_t)(k1 * CSZ + CSZ - 1)) * (BDIM * NDIM) + b * NDIM + tid] : 0.0f;
    }
    __syncthreads();

#define P2_STEP(KI, MB, VV)                                                        \
    {                                                                              \
        const int kcur = (KI);                                                     \
        if (tid < NDIM)                                                            \
            g_S[kcur * (BDIM * NDIM) + b * NDIM + tid] = s[tid];                   \
        float4 acc = make_float4(0.f, 0.f, 0.f, 0.f);                              \
        _Pragma("unroll")                                                          \
        for (int jj = 0; jj < 8; ++jj) {                                           \
            float sj = s[j0 + jj];                                                 \
            acc.x += MB[jj].x * sj; acc.y += MB[jj].y * sj;                        \
            acc.z += MB[jj].z * sj; acc.w += MB[jj].w * sj;                        \
        }                                                                          \
        /* re-issue this buffer's loads for kcur+2 (WAR on MB regs only) */        \
        const int k2 = (kcur + 2 < K) ? (kcur + 2) : (K - 1);                      \
        const float* M2 = g_P + ((size_t)(k2 * CSZ + CSZ - 1)) * (NDIM * NDIM);    \
        float vtmp = (tid < NDIM)                                                  \
            ? outy[((size_t)(k2 * CSZ + CSZ - 1)) * (BDIM * NDIM) + b * NDIM + tid]\
            : 0.0f;                                                                \
        _Pragma("unroll")                                                          \
        for (int jj = 0; jj < 8; ++jj)                                             \
            MB[jj] = *reinterpret_cast<const float4*>(M2 + (j0 + jj) * NDIM + i0); \
        *reinterpret_cast<float4*>(&part[q * NDIM + i0]) = acc;                    \
        __syncthreads();                                                           \
        if (tid < NDIM) {                                                          \
            float p[16];                                                           \
            _Pragma("unroll")                                                      \
            for (int qq = 0; qq < 16; ++qq) p[qq] = part[qq * NDIM + tid];         \
            float r = (((p[0] + p[1]) + (p[2] + p[3]))                             \
                     + ((p[4] + p[5]) + (p[6] + p[7])))                            \
                    + (((p[8] + p[9]) + (p[10] + p[11]))                           \
                     + ((p[12] + p[13]) + (p[14] + p[15])));                       \
            s[tid] = VV + r;                                                       \
        }                                                                          \
        VV = vtmp;                                                                 \
        __syncthreads();                                                           \
    }

    for (int k = 0; k < K; k += 2) {
        P2_STEP(k, mbA, vA);
        if (k + 1 < K) P2_STEP(k + 1, mbB, vB);
    }
#undef P2_STEP
}

// ---------------------------------------------------------------------------
// Pass 3: out[t][b][i] += sum_j P_t[i][j] * S_k[b][j].  grid = L, block = 256.
// (unchanged from R14)
// ---------------------------------------------------------------------------
__global__ __launch_bounds__(256, 1)
void pass3_apply(float* __restrict__ outp)
{
    __shared__ float sS[NDIM * 36];      // [j*36 + b]
    const int t   = blockIdx.x;
    const int k   = t >> 4;
    const int tid = threadIdx.x;

    for (int idx = tid; idx < NDIM * BDIM; idx += 256) {
        int b = idx >> 7, j = idx & 127;
        sS[j * 36 + b] = g_S[k * (BDIM * NDIM) + idx];
    }
    __syncthreads();

    const int i  = tid & 127;
    const int b0 = (tid >> 7) << 4;      // 0 or 16
    const size_t obase = (size_t)t * (BDIM * NDIM);

    ull acc[8];
#pragma unroll
    for (int q = 0; q < 8; ++q)
        acc[q] = pack2(outp[obase + (b0 + 2 * q) * NDIM + i],
                       outp[obase + (b0 + 2 * q + 1) * NDIM + i]);

    const float* P = g_P + (size_t)t * (NDIM * NDIM);
#pragma unroll 4
    for (int j = 0; j < NDIM; ++j) {
        float p = P[j * NDIM + i];
        ull pp = pack2(p, p);
        const ull* sp = reinterpret_cast<const ull*>(&sS[j * 36 + b0]);
#pragma unroll
        for (int q = 0; q < 8; ++q)
            acc[q] = fma2(pp, sp[q], acc[q]);
    }

#pragma unroll
    for (int q = 0; q < 8; ++q) {
        float2 r = unpack2(acc[q]);
        outp[obase + (b0 + 2 * q) * NDIM + i]     = r.x;
        outp[obase + (b0 + 2 * q + 1) * NDIM + i] = r.y;
    }
}

// ---------------------------------------------------------------------------
extern "C" void kernel_launch(void* const* d_in, const int* in_sizes, int n_in,
                              void* d_out, int out_size)
{
    int ia = 0;
    for (int i = 1; i < n_in; ++i)
        if (in_sizes[i] > in_sizes[ia]) ia = i;
    const float* A = (const float*)d_in[ia];
    const int L = in_sizes[ia] / (NDIM * NDIM);
    const float* inp = nullptr;
    const float* Bst = nullptr;
    for (int i = 0; i < n_in; ++i) {
        if (i == ia) continue;
        if (in_sizes[i] == L * BDIM) inp = (const float*)d_in[i];
        else                         Bst = (const float*)d_in[i];
    }
    float* out = (float*)d_out;
    const int K = L / CSZ;

    const int smem1 = (2 * NDIM * AP * 2) + (2 * XR * AP * 2) + (XR * AP * 4)
                    + (NDIM * NDIM * 4);
    cudaFuncSetAttribute(pass1_wmma, cudaFuncAttributeMaxDynamicSharedMemorySize, smem1);

    pass1_wmma<<<dim3(2, K), 512, smem1>>>(A, inp, Bst, out);
    pass2_scan<<<BDIM, 512>>>(out, K);
    pass3_apply<<<L, 256>>>(out);
}

// round 17
// speedup vs baseline: 1.5001x; 1.0064x over previous
#include <cuda_runtime.h>
#include <cuda_bf16.h>
#include <mma.h>
#include <cstdint>

using namespace nvcuda;

// HiPPO-LegS scan:  x_t = A_t x_{t-1} + inputs[t,b] * B_t,  x_{-1} = 0
//   inputs (L,32) f32; A_stacked (L,128,128) f32; B_stacked (L,128) f32
//   out (L,32,128) f32
//
// Pass 1 (wmma/HMMA): per chunk k (16 steps), per 80-column half h, evolve the
//   TRANSPOSED augmented state X (80 aug-cols x 128) via X <- X * A^T using
//   bf16 split-2 (3 MMA terms, fp32 acc). A_{t+1} prefetched with ONE
//   cp.async.bulk (UBLKCP) + mbarrier per step instead of 4096 LDGSTS.
// Pass 2: exact fp32 sequential scan over K chunk transitions -> g_S.
// Pass 3: out[t] += P_t * S_k  (f32x2 packed FMA, LDS.128 S reads).

#define NDIM 128
#define BDIM 32
#define CSZ  16
#define KMAX 64
#define LMAX 1024
#define XR   80      // augmented columns per block
#define AP   136     // padded leading dim (elements) for A/X/D tiles
#define ABYTES (NDIM * NDIM * 4)   // 64 KB per A_t

typedef unsigned long long ull;

__device__ float g_P[(size_t)LMAX * NDIM * NDIM];   // [t][col][i] = P_t[i][col]
__device__ float g_S[KMAX * BDIM * NDIM];           // [k][b][i] state BEFORE chunk k

// ---- packed fp32x2 helpers --------------------------------------------------
__device__ __forceinline__ ull fma2(ull a, ull b, ull c) {
    ull d;
    asm("fma.rn.f32x2 %0, %1, %2, %3;" : "=l"(d) : "l"(a), "l"(b), "l"(c));
    return d;
}
__device__ __forceinline__ ull pack2(float x, float y) {
    ull d;
    asm("mov.b64 %0, {%1, %2};" : "=l"(d) : "f"(x), "f"(y));
    return d;
}
__device__ __forceinline__ float2 unpack2(ull v) {
    float2 r;
    asm("mov.b64 {%0, %1}, %2;" : "=f"(r.x), "=f"(r.y) : "l"(v));
    return r;
}

// ---- smem addr / mbarrier / bulk-copy helpers (sm_90 baseline PTX) ----------
__device__ __forceinline__ uint32_t smem_u32(const void* p) {
    uint32_t a;
    asm("{ .reg .u64 t; cvta.to.shared.u64 t, %1; cvt.u32.u64 %0, t; }" : "=r"(a) : "l"(p));
    return a;
}
#define MBAR_INIT(mb, n) \
    asm volatile("mbarrier.init.shared.b64 [%0], %1;" :: "r"(mb), "r"(n) : "memory")
#define MBAR_EXPECT_TX(mb, bytes) \
    asm volatile("mbarrier.arrive.expect_tx.shared.b64 _, [%0], %1;" :: "r"(mb), "r"(bytes) : "memory")
#define MBAR_WAIT(mb, ph) do {                                                     \
    asm volatile("{\n\t.reg .pred P1;\n\t"                                         \
        "WAIT_LOOP_%=:\n\t"                                                        \
        "mbarrier.try_wait.parity.acquire.cta.shared::cta.b64 P1, [%0], %1, 0x989680;\n\t" \
        "@P1 bra.uni WAIT_DONE_%=;\n\t"                                            \
        "bra.uni WAIT_LOOP_%=;\n\t"                                                \
        "WAIT_DONE_%=:\n\t}"                                                       \
        :: "r"((uint32_t)(mb)), "r"((uint32_t)(ph)) : "memory");                   \
} while (0)
#define BULK_G2S(dst, src, bytes, mb) \
    asm volatile("cp.async.bulk.shared::cluster.global.mbarrier::complete_tx::bytes " \
                 "[%0], [%1], %2, [%3];" \
                 :: "r"(dst), "l"(src), "r"(bytes), "r"(mb) : "memory")

// ---------------------------------------------------------------------------
// Pass 1: grid = (2, K), block = 512 (16 warps).
// Warp w: wn = w&7 owns i-tile, wc = w>>3 owns ct tiles {0,1,2} or {3,4}.
// SMEM: Ahi/Alo (128 x AP bf16), Xhi/Xlo (80 x AP bf16), Dst (80 x AP f32),
//       Araw (128 x 128 f32 bulk-copy landing buffer). ~217 KB dynamic.
// ---------------------------------------------------------------------------
__global__ __launch_bounds__(512, 1)
void pass1_wmma(const float* __restrict__ A, const float* __restrict__ inp,
                const float* __restrict__ Bst, float* __restrict__ outp)
{
    extern __shared__ char smc[];
    __shared__ alignas(8) ull mbar_storage;
    __nv_bfloat16* Ahi = reinterpret_cast<__nv_bfloat16*>(smc);
    __nv_bfloat16* Alo = Ahi + NDIM * AP;
    __nv_bfloat16* Xhi = Alo + NDIM * AP;
    __nv_bfloat16* Xlo = Xhi + XR * AP;
    float*         Dst = reinterpret_cast<float*>(Xlo + XR * AP);
    float*         Araw = Dst + XR * AP;

    const int k   = blockIdx.y;
    const int h   = blockIdx.x;
    const int c0  = h * XR;
    const int tid = threadIdx.x;
    const int wid = tid >> 5;
    const int wn  = wid & 7;         // i-tile
    const int wc  = wid >> 3;        // ct group: 0 -> {0,1,2}, 1 -> {3,4}
    const int ct0 = wc ? 3 : 0;
    const int nct = wc ? 2 : 3;

    const uint32_t araw_s = smem_u32(Araw);
    const uint32_t mb     = smem_u32(&mbar_storage);

    if (tid == 0) MBAR_INIT(mb, 1);
    __syncthreads();
    // copy #0: A_{t0}
    if (tid == 0) {
        MBAR_EXPECT_TX(mb, ABYTES);
        BULK_G2S(araw_s, A + (size_t)(k * CSZ) * (NDIM * NDIM), ABYTES, mb);
    }

    // init X while copy #0 is in flight
    for (int idx = tid; idx < XR * NDIM; idx += 512) {
        int c = idx >> 7, j = idx & 127;
        Xhi[c * AP + j] = __float2bfloat16((c0 + c == j) ? 1.0f : 0.0f);
        Xlo[c * AP + j] = __float2bfloat16(0.0f);
    }

    MBAR_WAIT(mb, 0);
#pragma unroll
    for (int v = 0; v < 8; ++v) {
        int e = tid + v * 512;
        int r = e >> 5, c = (e & 31) << 2;
        float4 x = reinterpret_cast<const float4*>(Araw)[e];
        __nv_bfloat162 h0 = __floats2bfloat162_rn(x.x, x.y);
        __nv_bfloat162 h1 = __floats2bfloat162_rn(x.z, x.w);
        float2 f0 = __bfloat1622float2(h0);
        float2 f1 = __bfloat1622float2(h1);
        __nv_bfloat162 l0 = __floats2bfloat162_rn(x.x - f0.x, x.y - f0.y);
        __nv_bfloat162 l1 = __floats2bfloat162_rn(x.z - f1.x, x.w - f1.y);
        *reinterpret_cast<__nv_bfloat162*>(Ahi + r * AP + c)     = h0;
        *reinterpret_cast<__nv_bfloat162*>(Ahi + r * AP + c + 2) = h1;
        *reinterpret_cast<__nv_bfloat162*>(Alo + r * AP + c)     = l0;
        *reinterpret_cast<__nv_bfloat162*>(Alo + r * AP + c + 2) = l1;
    }
    __syncthreads();

    for (int lt = 0; lt < CSZ; ++lt) {
        const int t = k * CSZ + lt;

        // copy #(lt+1): A_{t+1}. Issued after the end-of-prev-step barrier, so
        // all converts of A_t from Araw are done and phase lt has completed.
        if (lt + 1 < CSZ && tid == 0) {
            MBAR_EXPECT_TX(mb, ABYTES);
            BULK_G2S(araw_s, A + (size_t)(t + 1) * (NDIM * NDIM), ABYTES, mb);
        }

        wmma::fragment<wmma::accumulator, 16, 16, 16, float> acc[3];
#pragma unroll
        for (int c = 0; c < 3; ++c)
            if (c < nct) wmma::fill_fragment(acc[c], 0.0f);

#pragma unroll
        for (int kk = 0; kk < 8; ++kk) {
            wmma::fragment<wmma::matrix_b, 16, 16, 16, __nv_bfloat16, wmma::col_major> bh, bl;
            wmma::load_matrix_sync(bh, Ahi + (size_t)(wn * 16) * AP + kk * 16, AP);
            wmma::load_matrix_sync(bl, Alo + (size_t)(wn * 16) * AP + kk * 16, AP);
#pragma unroll
            for (int c = 0; c < 3; ++c) {
                if (c < nct) {
                    const int ct = ct0 + c;
                    wmma::fragment<wmma::matrix_a, 16, 16, 16, __nv_bfloat16, wmma::row_major> ah, al;
                    wmma::load_matrix_sync(ah, Xhi + (size_t)(ct * 16) * AP + kk * 16, AP);
                    wmma::load_matrix_sync(al, Xlo + (size_t)(ct * 16) * AP + kk * 16, AP);
                    wmma::mma_sync(acc[c], ah, bh, acc[c]);
                    wmma::mma_sync(acc[c], al, bh, acc[c]);
                    wmma::mma_sync(acc[c], ah, bl, acc[c]);
                }
            }
        }
#pragma unroll
        for (int c = 0; c < 3; ++c)
            if (c < nct)
                wmma::store_matrix_sync(Dst + (size_t)((ct0 + c) * 16) * AP + wn * 16,
                                        acc[c], AP, wmma::mem_row_major);
        __syncthreads();   // all D tiles visible; all Ahi/Alo + X reads done

        // ---- epilogue: D -> (u-inject) -> g_P/out + X_{t+1} split ----------
        for (int idx = tid; idx < XR * NDIM; idx += 512) {
            int c = idx >> 7, i = idx & 127;
            int cg = c0 + c;
            float x = Dst[c * AP + i];
            if (cg >= NDIM)
                x += inp[t * BDIM + (cg - NDIM)] * Bst[t * NDIM + i];
            if (cg < NDIM)
                g_P[((size_t)t * NDIM + cg) * NDIM + i] = x;
            else
                outp[(size_t)t * (BDIM * NDIM) + (size_t)(cg - NDIM) * NDIM + i] = x;
            if (lt + 1 < CSZ) {
                __nv_bfloat16 hv = __float2bfloat16(x);
                Xhi[c * AP + i] = hv;
                Xlo[c * AP + i] = __float2bfloat16(x - __bfloat162float(hv));
            }
        }

        // ---- wait for A_{t+1}, convert Araw -> Ahi/Alo ----------------------
        if (lt + 1 < CSZ) {
            MBAR_WAIT(mb, (lt + 1) & 1);
#pragma unroll
            for (int v = 0; v < 8; ++v) {
                int e = tid + v * 512;
                int r = e >> 5, c = (e & 31) << 2;
                float4 x = reinterpret_cast<const float4*>(Araw)[e];
                __nv_bfloat162 h0 = __floats2bfloat162_rn(x.x, x.y);
                __nv_bfloat162 h1 = __floats2bfloat162_rn(x.z, x.w);
                float2 f0 = __bfloat1622float2(h0);
                float2 f1 = __bfloat1622float2(h1);
                __nv_bfloat162 l0 = __floats2bfloat162_rn(x.x - f0.x, x.y - f0.y);
                __nv_bfloat162 l1 = __floats2bfloat162_rn(x.z - f1.x, x.w - f1.y);
                *reinterpret_cast<__nv_bfloat162*>(Ahi + r * AP + c)     = h0;
                *reinterpret_cast<__nv_bfloat162*>(Ahi + r * AP + c + 2) = h1;
                *reinterpret_cast<__nv_bfloat162*>(Alo + r * AP + c)     = l0;
                *reinterpret_cast<__nv_bfloat162*>(Alo + r * AP + c + 2) = l1;
            }
        }
        __syncthreads();   // X_{t+1} + A_{t+1} ready; Araw reads complete
    }
}

// ---------------------------------------------------------------------------
// Pass 2: exact fp32 sequential scan; one block per batch column.
// grid = 32, block = 512. Unroll-2, two register buffer sets, no copies.
// ---------------------------------------------------------------------------
__global__ __launch_bounds__(512, 1)
void pass2_scan(const float* __restrict__ outy, int K)
{
    __shared__ float s[NDIM];
    __shared__ float part[16 * NDIM];
    const int b   = blockIdx.x;
    const int tid = threadIdx.x;
    const int i0  = (tid & 31) << 2;
    const int q   = tid >> 5;
    const int j0  = q << 3;

    if (tid < NDIM) s[tid] = 0.0f;

    float4 mbA[8], mbB[8];
    float vA, vB;
    {
        const float* M0 = g_P + ((size_t)(CSZ - 1)) * (NDIM * NDIM);
#pragma unroll
        for (int jj = 0; jj < 8; ++jj)
            mbA[jj] = *reinterpret_cast<const float4*>(M0 + (j0 + jj) * NDIM + i0);
        vA = (tid < NDIM)
            ? outy[((size_t)(CSZ - 1)) * (BDIM * NDIM) + b * NDIM + tid] : 0.0f;

        const int k1 = (1 < K) ? 1 : 0;
        const float* M1 = g_P + ((size_t)(k1 * CSZ + CSZ - 1)) * (NDIM * NDIM);
#pragma unroll
        for (int jj = 0; jj < 8; ++jj)
            mbB[jj] = *reinterpret_cast<const float4*>(M1 + (j0 + jj) * NDIM + i0);
        vB = (tid < NDIM)
            ? outy[((size_t)(k1 * CSZ + CSZ - 1)) * (BDIM * NDIM) + b * NDIM + tid] : 0.0f;
    }
    __syncthreads();

#define P2_STEP(KI, MB, VV)                                                        \
    {                                                                              \
        const int kcur = (KI);                                                     \
        if (tid < NDIM)                                                            \
            g_S[kcur * (BDIM * NDIM) + b * NDIM + tid] = s[tid];                   \
        float4 acc = make_float4(0.f, 0.f, 0.f, 0.f);                              \
        _Pragma("unroll")                                                          \
        for (int jj = 0; jj < 8; ++jj) {                                           \
            float sj = s[j0 + jj];                                                 \
            acc.x += MB[jj].x * sj; acc.y += MB[jj].y * sj;                        \
            acc.z += MB[jj].z * sj; acc.w += MB[jj].w * sj;                        \
        }                                                                          \
        const int k2 = (kcur + 2 < K) ? (kcur + 2) : (K - 1);                      \
        const float* M2 = g_P + ((size_t)(k2 * CSZ + CSZ - 1)) * (NDIM * NDIM);    \
        float vtmp = (tid < NDIM)                                                  \
            ? outy[((size_t)(k2 * CSZ + CSZ - 1)) * (BDIM * NDIM) + b * NDIM + tid]\
            : 0.0f;                                                                \
        _Pragma("unroll")                                                          \
        for (int jj = 0; jj < 8; ++jj)                                             \
            MB[jj] = *reinterpret_cast<const float4*>(M2 + (j0 + jj) * NDIM + i0); \
        *reinterpret_cast<float4*>(&part[q * NDIM + i0]) = acc;                    \
        __syncthreads();                                                           \
        if (tid < NDIM) {                                                          \
            float p[16];                                                           \
            _Pragma("unroll")                                                      \
            for (int qq = 0; qq < 16; ++qq) p[qq] = part[qq * NDIM + tid];         \
            float r = (((p[0] + p[1]) + (p[2] + p[3]))                             \
                     + ((p[4] + p[5]) + (p[6] + p[7])))                            \
                    + (((p[8] + p[9]) + (p[10] + p[11]))                           \
                     + ((p[12] + p[13]) + (p[14] + p[15])));                       \
            s[tid] = VV + r;                                                       \
        }                                                                          \
        VV = vtmp;                                                                 \
        __syncthreads();                                                           \
    }

    for (int k = 0; k < K; k += 2) {
        P2_STEP(k, mbA, vA);
        if (k + 1 < K) P2_STEP(k + 1, mbB, vB);
    }
#undef P2_STEP
}

// ---------------------------------------------------------------------------
// Pass 3: out[t][b][i] += sum_j P_t[i][j] * S_k[b][j].  grid = L, block = 256.
// S read as LDS.128 broadcast (4 wavefronts/warp/j instead of 8).
// ---------------------------------------------------------------------------
__global__ __launch_bounds__(256, 1)
void pass3_apply(float* __restrict__ outp)
{
    __shared__ float sS[NDIM * 36];      // [j*36 + b]; 36 % 4 == 0 -> 16B rows
    const int t   = blockIdx.x;
    const int k   = t >> 4;
    const int tid = threadIdx.x;

    for (int idx = tid; idx < NDIM * BDIM; idx += 256) {
        int b = idx >> 7, j = idx & 127;
        sS[j * 36 + b] = g_S[k * (BDIM * NDIM) + idx];
    }
    __syncthreads();

    const int i  = tid & 127;
    const int b0 = (tid >> 7) << 4;      // 0 or 16
    const size_t obase = (size_t)t * (BDIM * NDIM);

    ull acc[8];
#pragma unroll
    for (int q = 0; q < 8; ++q)
        acc[q] = pack2(outp[obase + (b0 + 2 * q) * NDIM + i],
                       outp[obase + (b0 + 2 * q + 1) * NDIM + i]);

    const float* P = g_P + (size_t)t * (NDIM * NDIM);
#pragma unroll 4
    for (int j = 0; j < NDIM; ++j) {
        float p = P[j * NDIM + i];
        ull pp = pack2(p, p);
        const ulonglong2* sp = reinterpret_cast<const ulonglong2*>(&sS[j * 36 + b0]);
#pragma unroll
        for (int q = 0; q < 4; ++q) {
            ulonglong2 sv = sp[q];                      // LDS.128 broadcast
            acc[2 * q]     = fma2(pp, sv.x, acc[2 * q]);
            acc[2 * q + 1] = fma2(pp, sv.y, acc[2 * q + 1]);
        }
    }

#pragma unroll
    for (int q = 0; q < 8; ++q) {
        float2 r = unpack2(acc[q]);
        outp[obase + (b0 + 2 * q) * NDIM + i]     = r.x;
        outp[obase + (b0 + 2 * q + 1) * NDIM + i] = r.y;
    }
}

// ---------------------------------------------------------------------------
extern "C" void kernel_launch(void* const* d_in, const int* in_sizes, int n_in,
                              void* d_out, int out_size)
{
    int ia = 0;
    for (int i = 1; i < n_in; ++i)
        if (in_sizes[i] > in_sizes[ia]) ia = i;
    const float* A = (const float*)d_in[ia];
    const int L = in_sizes[ia] / (NDIM * NDIM);
    const float* inp = nullptr;
    const float* Bst = nullptr;
    for (int i = 0; i < n_in; ++i) {
        if (i == ia) continue;
        if (in_sizes[i] == L * BDIM) inp = (const float*)d_in[i];
        else                         Bst = (const float*)d_in[i];
    }
    float* out = (float*)d_out;
    const int K = L / CSZ;

    const int smem1 = (2 * NDIM * AP * 2) + (2 * XR * AP * 2) + (XR * AP * 4)
                    + (NDIM * NDIM * 4);
    cudaFuncSetAttribute(pass1_wmma, cudaFuncAttributeMaxDynamicSharedMemorySize, smem1);

    pass1_wmma<<<dim3(2, K), 512, smem1>>>(A, inp, Bst, out);
    pass2_scan<<<BDIM, 512>>>(out, K);
    pass3_apply<<<L, 256>>>(out);
}